// round 13
// baseline (speedup 1.0000x reference)
#include <cuda_runtime.h>
#include <cuda_bf16.h>
#include <math.h>

#define N_NODES 10000
#define N_EDGES 160000
#define H 128
#define E_RBF 20
#define CUTOFF 5.0f
#define PI_F 3.14159265358979f

typedef unsigned long long u64;
typedef unsigned int u32;

// ---------------- scratch ----------------
__device__ float g_ns[N_NODES * H];
__device__ float g_nvA[N_NODES * 3 * H];
__device__ float g_nvB[N_NODES * 3 * H];
__device__ float g_big[N_NODES * 3 * H];
__device__ float g_UV[N_NODES * 3 * 256];
__device__ float g_UVw[3 * 128 * 256];
__device__ float g_UVb[3 * 256];
// CSR sort + sorted-position per-edge precompute
__device__ int    g_count[N_NODES];
__device__ int    g_offset[N_NODES + 1];
__device__ int    g_ssrc[N_EDGES];
__device__ int    g_sdst[N_EDGES];
__device__ float4 g_eunit[N_EDGES];  // {ux, uy, uz, fcut}
__device__ float4 g_epre[N_EDGES];   // {sin(x), 2cos(x), fcut/d, 0}

// ---------------- helpers ----------------
__device__ __forceinline__ u64 pack2(float x, float y) {
    u64 r; asm("mov.b64 %0,{%1,%2};" : "=l"(r) : "f"(x), "f"(y)); return r;
}
__device__ __forceinline__ void unpack2(u64 v, float& x, float& y) {
    asm("mov.b64 {%0,%1},%2;" : "=f"(x), "=f"(y) : "l"(v));
}
__device__ __forceinline__ u64 fma2(u64 a, u64 b, u64 c) {
    u64 d; asm("fma.rn.f32x2 %0,%1,%2,%3;" : "=l"(d) : "l"(a), "l"(b), "l"(c)); return d;
}
__device__ __forceinline__ u64 mul2(u64 a, u64 b) {
    u64 d; asm("mul.rn.f32x2 %0,%1,%2;" : "=l"(d) : "l"(a), "l"(b)); return d;
}
__device__ __forceinline__ void red4(float* p, float x, float y, float z, float w) {
    asm volatile("red.global.add.v4.f32 [%0], {%1,%2,%3,%4};"
                 :: "l"(p), "f"(x), "f"(y), "f"(z), "f"(w) : "memory");
}
__device__ __forceinline__ float silu_f(float x) { return x / (1.0f + expf(-x)); }
__device__ __forceinline__ float tf32rna(float x) {
    u32 r; asm("cvt.rna.tf32.f32 %0, %1;" : "=r"(r) : "f"(x));
    return __uint_as_float(r);
}

#define MMA_TF32(cc, aa, bb)                                                      \
    asm volatile("mma.sync.aligned.m16n8k8.row.col.f32.tf32.tf32.f32 "            \
                 "{%0,%1,%2,%3},{%4,%5,%6,%7},{%8,%9},{%0,%1,%2,%3};"             \
                 : "+f"((cc)[0]), "+f"((cc)[1]), "+f"((cc)[2]), "+f"((cc)[3])     \
                 : "r"((aa)[0]), "r"((aa)[1]), "r"((aa)[2]), "r"((aa)[3]),        \
                   "r"((bb)[0]), "r"((bb)[1]))

// ---------------- init ----------------
__global__ void init_kernel(const int* __restrict__ z, const float* __restrict__ embed) {
    int i = blockIdx.x * blockDim.x + threadIdx.x;
    if (i >= N_NODES * 3 * H) return;
    g_nvA[i] = 0.0f;
    g_nvB[i] = 0.0f;
    if (i < N_NODES * H) {
        int n = i >> 7, h = i & 127;
        g_ns[i] = embed[z[n] * H + h];
    }
    if (i < N_NODES) g_count[i] = 0;
}

// ---------------- dst histogram ----------------
__global__ void hist_kernel(const int* __restrict__ edge) {
    int e = blockIdx.x * blockDim.x + threadIdx.x;
    if (e >= N_EDGES) return;
    atomicAdd(&g_count[edge[2 * e]], 1);
}

// ---------------- exclusive scan of counts ----------------
__global__ __launch_bounds__(1024)
void scan_kernel() {
    __shared__ int part[1024];
    const int t = threadIdx.x;
    const int CH = (N_NODES + 1023) / 1024;
    const int base = t * CH;
    int s = 0;
    for (int i = 0; i < CH; i++) {
        int idx = base + i;
        if (idx < N_NODES) s += g_count[idx];
    }
    part[t] = s;
    __syncthreads();
    for (int off = 1; off < 1024; off <<= 1) {
        int v = (t >= off) ? part[t - off] : 0;
        __syncthreads();
        part[t] += v;
        __syncthreads();
    }
    int run = (t > 0) ? part[t - 1] : 0;
    for (int i = 0; i < CH; i++) {
        int idx = base + i;
        if (idx < N_NODES) {
            g_offset[idx] = run;
            run += g_count[idx];
            g_count[idx] = 0;
        }
    }
    if (t == 1023) g_offset[N_NODES] = part[1023];
}

// ---------------- build sorted arrays + per-edge invariants ----------------
__global__ void build_kernel(const int* __restrict__ edge,
                             const float* __restrict__ ediff,
                             const float* __restrict__ edist) {
    int e = blockIdx.x * blockDim.x + threadIdx.x;
    if (e >= N_EDGES) return;
    int dst = edge[2 * e], src = edge[2 * e + 1];
    int pos = g_offset[dst] + atomicAdd(&g_count[dst], 1);
    float d = edist[e];
    float sn, cs;
    sincosf(d * (PI_F / CUTOFF), &sn, &cs);
    float fcv = (d < CUTOFF) ? 0.5f * (cs + 1.0f) : 0.0f;
    float inv = 1.0f / d;
    g_ssrc[pos]  = src;
    g_sdst[pos]  = dst;
    g_eunit[pos] = make_float4(ediff[3 * e] * inv, ediff[3 * e + 1] * inv,
                               ediff[3 * e + 2] * inv, fcv);
    g_epre[pos]  = make_float4(sn, 2.0f * cs, inv * fcv, 0.0f);
}

// ---------------- pack [U_w | V_w] ----------------
__global__ void pack_uv_kernel(const float* __restrict__ Uw, const float* __restrict__ Ub,
                               const float* __restrict__ Vw, const float* __restrict__ Vb) {
    int i = blockIdx.x * blockDim.x + threadIdx.x;
    if (i < 3 * 128 * 256) {
        int l = i / (128 * 256), r = (i / 256) & 127, c = i & 255;
        g_UVw[i] = (c < 128) ? Uw[(size_t)l * 16384 + r * 128 + c]
                             : Vw[(size_t)l * 16384 + r * 128 + (c - 128)];
    }
    if (i < 3 * 256) {
        int l = i / 256, c = i & 255;
        g_UVb[i] = (c < 128) ? Ub[l * 128 + c] : Vb[l * 128 + (c - 128)];
    }
}

// ---------------- TF32 tensor-core GEMM (UV; proven structure) ----------------
template<int BM, bool SILU>
__global__ __launch_bounds__(256, 2)
void mma_gemm(const float* __restrict__ A, const float* __restrict__ B,
              const float* __restrict__ bias, float* __restrict__ C,
              int M, int N, int K) {
    constexpr int MT = BM / 32;
    __shared__ float As[2][BM][20];
    __shared__ float Bs[2][16][136];
    const int t    = threadIdx.x;
    const int w    = t >> 5, lane = t & 31;
    const int g    = lane >> 2, tg = lane & 3;
    const int wm   = (w & 1) * (BM / 2);
    const int wn   = (w >> 1) * 32;
    const int m0   = blockIdx.y * BM;
    const int n0   = blockIdx.x * 128;

    float c[MT][4][4];
#pragma unroll
    for (int i = 0; i < MT; i++)
#pragma unroll
        for (int j = 0; j < 4; j++)
#pragma unroll
            for (int q = 0; q < 4; q++) c[i][j][q] = 0.0f;

    constexpr int ALD = (BM == 128) ? 2 : 1;
    int ar[2], ak[2];
#pragma unroll
    for (int i = 0; i < ALD; i++) {
        int s = t * ALD + i;
        ar[i] = s >> 2;
        ak[i] = (s & 3) << 2;
    }
    const int bs  = t * 2;
    const int bk0 = bs >> 5,        bn0 = (bs & 31) << 2;
    const int bk1 = (bs + 1) >> 5,  bn1 = ((bs + 1) & 31) << 2;

    float4 va[2], vb0, vb1;
    const float4 z4 = make_float4(0.f, 0.f, 0.f, 0.f);

#pragma unroll
    for (int i = 0; i < ALD; i++)
        va[i] = (m0 + ar[i] < M) ? *(const float4*)(A + (size_t)(m0 + ar[i]) * K + ak[i]) : z4;
    vb0 = *(const float4*)(B + (size_t)bk0 * N + n0 + bn0);
    vb1 = *(const float4*)(B + (size_t)bk1 * N + n0 + bn1);
    {
#pragma unroll
        for (int i = 0; i < ALD; i++) {
            float* p = &As[0][ar[i]][ak[i]];
            p[0] = tf32rna(va[i].x); p[1] = tf32rna(va[i].y);
            p[2] = tf32rna(va[i].z); p[3] = tf32rna(va[i].w);
        }
        float* q0 = &Bs[0][bk0][bn0];
        q0[0] = tf32rna(vb0.x); q0[1] = tf32rna(vb0.y); q0[2] = tf32rna(vb0.z); q0[3] = tf32rna(vb0.w);
        float* q1 = &Bs[0][bk1][bn1];
        q1[0] = tf32rna(vb1.x); q1[1] = tf32rna(vb1.y); q1[2] = tf32rna(vb1.z); q1[3] = tf32rna(vb1.w);
    }
    __syncthreads();

    const int nk = K >> 4;
    for (int kt = 0; kt < nk; kt++) {
        const int s = kt & 1;
        if (kt + 1 < nk) {
            const int k0 = (kt + 1) << 4;
#pragma unroll
            for (int i = 0; i < ALD; i++)
                va[i] = (m0 + ar[i] < M) ? *(const float4*)(A + (size_t)(m0 + ar[i]) * K + k0 + ak[i]) : z4;
            vb0 = *(const float4*)(B + (size_t)(k0 + bk0) * N + n0 + bn0);
            vb1 = *(const float4*)(B + (size_t)(k0 + bk1) * N + n0 + bn1);
        }
#pragma unroll
        for (int kk = 0; kk < 2; kk++) {
            const int kb = kk * 8;
            u32 a[MT][4], b[4][2];
#pragma unroll
            for (int mt = 0; mt < MT; mt++) {
                const int r = wm + mt * 16 + g;
                a[mt][0] = __float_as_uint(As[s][r][kb + tg]);
                a[mt][1] = __float_as_uint(As[s][r + 8][kb + tg]);
                a[mt][2] = __float_as_uint(As[s][r][kb + tg + 4]);
                a[mt][3] = __float_as_uint(As[s][r + 8][kb + tg + 4]);
            }
#pragma unroll
            for (int nt = 0; nt < 4; nt++) {
                const int col = wn + nt * 8 + g;
                b[nt][0] = __float_as_uint(Bs[s][kb + tg][col]);
                b[nt][1] = __float_as_uint(Bs[s][kb + tg + 4][col]);
            }
#pragma unroll
            for (int mt = 0; mt < MT; mt++)
#pragma unroll
                for (int nt = 0; nt < 4; nt++)
                    MMA_TF32(c[mt][nt], a[mt], b[nt]);
        }
        if (kt + 1 < nk) {
            const int ss = s ^ 1;
#pragma unroll
            for (int i = 0; i < ALD; i++) {
                float* p = &As[ss][ar[i]][ak[i]];
                p[0] = tf32rna(va[i].x); p[1] = tf32rna(va[i].y);
                p[2] = tf32rna(va[i].z); p[3] = tf32rna(va[i].w);
            }
            float* q0 = &Bs[ss][bk0][bn0];
            q0[0] = tf32rna(vb0.x); q0[1] = tf32rna(vb0.y); q0[2] = tf32rna(vb0.z); q0[3] = tf32rna(vb0.w);
            float* q1 = &Bs[ss][bk1][bn1];
            q1[0] = tf32rna(vb1.x); q1[1] = tf32rna(vb1.y); q1[2] = tf32rna(vb1.z); q1[3] = tf32rna(vb1.w);
            __syncthreads();
        }
    }

#pragma unroll
    for (int nt = 0; nt < 4; nt++) {
        const int col = n0 + wn + nt * 8 + 2 * tg;
        const float2 bb = *(const float2*)&bias[col];
#pragma unroll
        for (int mt = 0; mt < MT; mt++) {
            const int r0 = m0 + wm + mt * 16 + g;
            float v0 = c[mt][nt][0] + bb.x, v1 = c[mt][nt][1] + bb.y;
            float v2 = c[mt][nt][2] + bb.x, v3 = c[mt][nt][3] + bb.y;
            if (SILU) { v0 = silu_f(v0); v1 = silu_f(v1); v2 = silu_f(v2); v3 = silu_f(v3); }
            if (r0 < M)     *(float2*)(C + (size_t)r0 * N + col)       = make_float2(v0, v1);
            if (r0 + 8 < M) *(float2*)(C + (size_t)(r0 + 8) * N + col) = make_float2(v2, v3);
        }
    }
}

// ---------------- fused 2-stage MLP with optional update/norm prologues ----------------
// UPD: 0=none, 1=full gated update before stage1, 2=ns-only update (readout).
// NORM: A built on the fly as [ |Vv|(128) | ns(128) ] (upd-MLP); A param unused.
// COHERENCE: when UPD != 0, the prologue writes g_ns with plain stores and stage 1
// re-reads those addresses, so the A tile MUST be read through a plain (non-restrict)
// pointer to g_ns — never through the __restrict__ A param (nc-loads are stale).
#define FUSED_SMEM 68608

__device__ __forceinline__ float4 load_mlpin(int node, int col4, int M) {
    if (node >= M) return make_float4(0.f, 0.f, 0.f, 0.f);
    if (col4 < 128) {
        size_t b = (size_t)(3 * node) * 256 + 128 + col4;
        float4 u0 = *(const float4*)&g_UV[b];
        float4 u1 = *(const float4*)&g_UV[b + 256];
        float4 u2 = *(const float4*)&g_UV[b + 512];
        return make_float4(
            sqrtf(u0.x * u0.x + u1.x * u1.x + u2.x * u2.x),
            sqrtf(u0.y * u0.y + u1.y * u1.y + u2.y * u2.y),
            sqrtf(u0.z * u0.z + u1.z * u1.z + u2.z * u2.z),
            sqrtf(u0.w * u0.w + u1.w * u1.w + u2.w * u2.w));
    }
    return *(const float4*)&g_ns[(size_t)node * 128 + (col4 - 128)];
}

template<int K1, int NB, int UPD, bool NORM>
__global__ __launch_bounds__(256, 2)
void fused_mlp(const float* __restrict__ A, const float* __restrict__ W1,
               const float* __restrict__ b1, const float* __restrict__ W2,
               const float* __restrict__ b2, float* __restrict__ C, int M) {
    extern __shared__ char fsm[];
    float (*As)[64][20]  = (float(*)[64][20])fsm;
    float (*Bs)[16][136] = (float(*)[16][136])(fsm + 10240);
    float (*Hs)[64][20]  = (float(*)[64][20])(fsm + 27648);

    const int t = threadIdx.x;
    const int w = t >> 5, lane = t & 31;
    const int g = lane >> 2, tg = lane & 3;
    const int wm = (w & 1) * 32;
    const int wn = (w >> 1) * 32;
    const int m0 = blockIdx.x * 64;
    const int N2 = NB * 128;

    // ---------- optional gated-update prologue (rows owned by this CTA only) ----------
    if (UPD) {
#pragma unroll 4
        for (int j = 0; j < 32; j++) {
            int i = j * 256 + t;
            int r = i >> 7, h = i & 127;
            int node = m0 + r;
            if (node < M) {
                const float* mo = g_big + (size_t)node * 384;
                float a_vv = mo[h], a_sv = mo[128 + h], a_ss = mo[256 + h];
                size_t uvb = (size_t)(3 * node) * 256 + h;
                size_t nvb = (size_t)node * 384 + h;
                float dot = 0.0f;
#pragma unroll
                for (int d = 0; d < 3; d++) {
                    float u = g_UV[uvb + d * 256];
                    float v = g_UV[uvb + d * 256 + 128];
                    dot = fmaf(u, v, dot);
                    if (UPD == 1) {
                        float nvnew = g_nvB[nvb + d * 128] + a_vv * u;
                        g_nvA[nvb + d * 128] = nvnew;
                        g_nvB[nvb + d * 128] = nvnew;
                    }
                }
                g_ns[(size_t)node * 128 + h] += a_sv * dot + a_ss;
            }
        }
        __syncthreads();
    }

    // Stage-1 A source: plain pointer to g_ns when the prologue just wrote it
    // (avoids stale ld.global.nc through the __restrict__ param).
    const float* Aeff = (UPD != 0) ? (const float*)g_ns : A;

    const int ar  = t >> 2,          ak  = (t & 3) << 2;
    const int bs  = t * 2;
    const int bk0 = bs >> 5,         bn0 = (bs & 31) << 2;
    const int bk1 = (bs + 1) >> 5,   bn1 = ((bs + 1) & 31) << 2;
    const float4 z4 = make_float4(0.f, 0.f, 0.f, 0.f);

    float c[2][4][4];
#pragma unroll
    for (int i = 0; i < 2; i++)
#pragma unroll
        for (int j = 0; j < 4; j++)
#pragma unroll
            for (int q = 0; q < 4; q++) c[i][j][q] = 0.0f;

    // ---------- stage 1 ----------
    float4 va, vb0, vb1;
    va  = NORM ? load_mlpin(m0 + ar, ak, M)
               : ((m0 + ar < M) ? *(const float4*)(Aeff + (size_t)(m0 + ar) * K1 + ak) : z4);
    vb0 = *(const float4*)(W1 + (size_t)bk0 * 128 + bn0);
    vb1 = *(const float4*)(W1 + (size_t)bk1 * 128 + bn1);
    {
        float* p = &As[0][ar][ak];
        p[0] = tf32rna(va.x); p[1] = tf32rna(va.y); p[2] = tf32rna(va.z); p[3] = tf32rna(va.w);
        float* q0 = &Bs[0][bk0][bn0];
        q0[0] = tf32rna(vb0.x); q0[1] = tf32rna(vb0.y); q0[2] = tf32rna(vb0.z); q0[3] = tf32rna(vb0.w);
        float* q1 = &Bs[0][bk1][bn1];
        q1[0] = tf32rna(vb1.x); q1[1] = tf32rna(vb1.y); q1[2] = tf32rna(vb1.z); q1[3] = tf32rna(vb1.w);
    }
    __syncthreads();

    const int nk1 = K1 >> 4;
    for (int kt = 0; kt < nk1; kt++) {
        const int s = kt & 1;
        if (kt + 1 < nk1) {
            const int k0 = (kt + 1) << 4;
            va  = NORM ? load_mlpin(m0 + ar, k0 + ak, M)
                       : ((m0 + ar < M) ? *(const float4*)(Aeff + (size_t)(m0 + ar) * K1 + k0 + ak) : z4);
            vb0 = *(const float4*)(W1 + (size_t)(k0 + bk0) * 128 + bn0);
            vb1 = *(const float4*)(W1 + (size_t)(k0 + bk1) * 128 + bn1);
        }
#pragma unroll
        for (int kk = 0; kk < 2; kk++) {
            const int kb = kk * 8;
            u32 a[2][4], b[4][2];
#pragma unroll
            for (int mt = 0; mt < 2; mt++) {
                const int r = wm + mt * 16 + g;
                a[mt][0] = __float_as_uint(As[s][r][kb + tg]);
                a[mt][1] = __float_as_uint(As[s][r + 8][kb + tg]);
                a[mt][2] = __float_as_uint(As[s][r][kb + tg + 4]);
                a[mt][3] = __float_as_uint(As[s][r + 8][kb + tg + 4]);
            }
#pragma unroll
            for (int nt = 0; nt < 4; nt++) {
                const int col = wn + nt * 8 + g;
                b[nt][0] = __float_as_uint(Bs[s][kb + tg][col]);
                b[nt][1] = __float_as_uint(Bs[s][kb + tg + 4][col]);
            }
#pragma unroll
            for (int mt = 0; mt < 2; mt++)
#pragma unroll
                for (int nt = 0; nt < 4; nt++)
                    MMA_TF32(c[mt][nt], a[mt], b[nt]);
        }
        if (kt + 1 < nk1) {
            const int ss = s ^ 1;
            float* p = &As[ss][ar][ak];
            p[0] = tf32rna(va.x); p[1] = tf32rna(va.y); p[2] = tf32rna(va.z); p[3] = tf32rna(va.w);
            float* q0 = &Bs[ss][bk0][bn0];
            q0[0] = tf32rna(vb0.x); q0[1] = tf32rna(vb0.y); q0[2] = tf32rna(vb0.z); q0[3] = tf32rna(vb0.w);
            float* q1 = &Bs[ss][bk1][bn1];
            q1[0] = tf32rna(vb1.x); q1[1] = tf32rna(vb1.y); q1[2] = tf32rna(vb1.z); q1[3] = tf32rna(vb1.w);
            __syncthreads();
        }
    }

    // epilogue stage 1 -> Hs (bias + silu + tf32 rounding)
    __syncthreads();
#pragma unroll
    for (int nt = 0; nt < 4; nt++) {
        const int col = wn + nt * 8 + 2 * tg;
        const float2 bb = *(const float2*)&b1[col];
        const int ch = col >> 4, cl = col & 15;
#pragma unroll
        for (int mt = 0; mt < 2; mt++) {
            const int r0 = wm + mt * 16 + g;
            float v0 = silu_f(c[mt][nt][0] + bb.x), v1 = silu_f(c[mt][nt][1] + bb.y);
            float v2 = silu_f(c[mt][nt][2] + bb.x), v3 = silu_f(c[mt][nt][3] + bb.y);
            *(float2*)&Hs[ch][r0][cl]     = make_float2(tf32rna(v0), tf32rna(v1));
            *(float2*)&Hs[ch][r0 + 8][cl] = make_float2(tf32rna(v2), tf32rna(v3));
        }
    }
    __syncthreads();

    // ---------- stage 2: NB blocks of 128 cols ----------
    for (int nb = 0; nb < NB; nb++) {
#pragma unroll
        for (int i = 0; i < 2; i++)
#pragma unroll
            for (int j = 0; j < 4; j++)
#pragma unroll
                for (int q = 0; q < 4; q++) c[i][j][q] = 0.0f;

        vb0 = *(const float4*)(W2 + (size_t)bk0 * N2 + nb * 128 + bn0);
        vb1 = *(const float4*)(W2 + (size_t)bk1 * N2 + nb * 128 + bn1);
        {
            float* q0 = &Bs[0][bk0][bn0];
            q0[0] = tf32rna(vb0.x); q0[1] = tf32rna(vb0.y); q0[2] = tf32rna(vb0.z); q0[3] = tf32rna(vb0.w);
            float* q1 = &Bs[0][bk1][bn1];
            q1[0] = tf32rna(vb1.x); q1[1] = tf32rna(vb1.y); q1[2] = tf32rna(vb1.z); q1[3] = tf32rna(vb1.w);
        }
        __syncthreads();

        for (int kt = 0; kt < 8; kt++) {
            const int s = kt & 1;
            if (kt + 1 < 8) {
                const int k0 = (kt + 1) << 4;
                vb0 = *(const float4*)(W2 + (size_t)(k0 + bk0) * N2 + nb * 128 + bn0);
                vb1 = *(const float4*)(W2 + (size_t)(k0 + bk1) * N2 + nb * 128 + bn1);
            }
#pragma unroll
            for (int kk = 0; kk < 2; kk++) {
                const int kb = kk * 8;
                u32 a[2][4], b[4][2];
#pragma unroll
                for (int mt = 0; mt < 2; mt++) {
                    const int r = wm + mt * 16 + g;
                    a[mt][0] = __float_as_uint(Hs[kt][r][kb + tg]);
                    a[mt][1] = __float_as_uint(Hs[kt][r + 8][kb + tg]);
                    a[mt][2] = __float_as_uint(Hs[kt][r][kb + tg + 4]);
                    a[mt][3] = __float_as_uint(Hs[kt][r + 8][kb + tg + 4]);
                }
#pragma unroll
                for (int nt = 0; nt < 4; nt++) {
                    const int col = wn + nt * 8 + g;
                    b[nt][0] = __float_as_uint(Bs[s][kb + tg][col]);
                    b[nt][1] = __float_as_uint(Bs[s][kb + tg + 4][col]);
                }
#pragma unroll
                for (int mt = 0; mt < 2; mt++)
#pragma unroll
                    for (int nt = 0; nt < 4; nt++)
                        MMA_TF32(c[mt][nt], a[mt], b[nt]);
            }
            if (kt + 1 < 8) {
                const int ss = s ^ 1;
                float* q0 = &Bs[ss][bk0][bn0];
                q0[0] = tf32rna(vb0.x); q0[1] = tf32rna(vb0.y); q0[2] = tf32rna(vb0.z); q0[3] = tf32rna(vb0.w);
                float* q1 = &Bs[ss][bk1][bn1];
                q1[0] = tf32rna(vb1.x); q1[1] = tf32rna(vb1.y); q1[2] = tf32rna(vb1.z); q1[3] = tf32rna(vb1.w);
                __syncthreads();
            }
        }

#pragma unroll
        for (int nt = 0; nt < 4; nt++) {
            const int col = wn + nt * 8 + 2 * tg;
            const float2 bb = *(const float2*)&b2[nb * 128 + col];
#pragma unroll
            for (int mt = 0; mt < 2; mt++) {
                const int r0 = m0 + wm + mt * 16 + g;
                float v0 = c[mt][nt][0] + bb.x, v1 = c[mt][nt][1] + bb.y;
                float v2 = c[mt][nt][2] + bb.x, v3 = c[mt][nt][3] + bb.y;
                if (r0 < M)
                    *(float2*)(C + (size_t)r0 * N2 + nb * 128 + col) = make_float2(v0, v1);
                if (r0 + 8 < M)
                    *(float2*)(C + (size_t)(r0 + 8) * N2 + nb * 128 + col) = make_float2(v2, v3);
            }
        }
        __syncthreads();
    }
}

// ---------------- edge kernel: 16 sorted edges/warp, dst-segmented reduction ----------------
__global__ __launch_bounds__(256, 2)
void edge_seg_kernel(const float* __restrict__ Wf,
                     const float* __restrict__ bf,
                     const float* __restrict__ so,
                     const float* __restrict__ nv_r,
                     float* __restrict__ ns_acc,
                     float* __restrict__ nv_acc)
{
    __shared__ float sW[E_RBF * 384 + 384];
    for (int i = threadIdx.x; i < E_RBF * 384; i += blockDim.x) sW[i] = Wf[i];
    for (int i = threadIdx.x; i < 384; i += blockDim.x) sW[E_RBF * 384 + i] = bf[i];
    __syncthreads();
    const u64* sW2 = (const u64*)sW;
    const u64* sB2 = (const u64*)(sW + E_RBF * 384);

    const int lane = threadIdx.x & 31;
    const int l2   = lane * 2;
    const int warp = (blockIdx.x * blockDim.x + threadIdx.x) >> 5;
    const int jb   = warp * 16;
    if (jb >= N_EDGES) return;

    const u64 Z = pack2(0.0f, 0.0f);
    u64 ans0 = Z, ans1 = Z;
    u64 anv0 = Z, anv1 = Z, anv2 = Z, anv3 = Z, anv4 = Z, anv5 = Z;
    int cur = g_sdst[jb];

#define FLUSH(D)                                                                  \
    do {                                                                          \
        float f0, f1, f2, f3;                                                     \
        unpack2(ans0, f0, f1); unpack2(ans1, f2, f3);                             \
        red4(ns_acc + (size_t)(D) * H + 4 * lane, f0, f1, f2, f3);                \
        float* bp_ = nv_acc + (size_t)(D) * 384 + 4 * lane;                       \
        unpack2(anv0, f0, f1); unpack2(anv1, f2, f3); red4(bp_,       f0, f1, f2, f3); \
        unpack2(anv2, f0, f1); unpack2(anv3, f2, f3); red4(bp_ + 128, f0, f1, f2, f3); \
        unpack2(anv4, f0, f1); unpack2(anv5, f2, f3); red4(bp_ + 256, f0, f1, f2, f3); \
        ans0 = ans1 = anv0 = anv1 = anv2 = anv3 = anv4 = anv5 = Z;                \
    } while (0)

    for (int j = jb; j < jb + 16; j += 4) {
        int src[4], dst[4];
        float invf[4], sC[4], sP[4], c2[4], ux[4], uy[4], uz[4];
        u64 a0a[4], a0b[4], a1a[4], a1b[4], a2a[4], a2b[4];
#pragma unroll
        for (int u = 0; u < 4; u++) {
            int p = j + u;
            src[u] = g_ssrc[p];
            dst[u] = g_sdst[p];
            float4 un = g_eunit[p];
            float4 pr = g_epre[p];
            ux[u] = un.x; uy[u] = un.y; uz[u] = un.z;
            float fcv = un.w;
            invf[u] = pr.z; sC[u] = pr.x; sP[u] = 0.0f; c2[u] = pr.y;
            u64 fcp = pack2(fcv, fcv);
            a0a[u] = mul2(sB2[l2],       fcp); a0b[u] = mul2(sB2[l2 + 1],       fcp);
            a1a[u] = mul2(sB2[64 + l2],  fcp); a1b[u] = mul2(sB2[64 + l2 + 1],  fcp);
            a2a[u] = mul2(sB2[128 + l2], fcp); a2b[u] = mul2(sB2[128 + l2 + 1], fcp);
        }
#pragma unroll 4
        for (int n = 0; n < E_RBF; n++) {
            const u64* wn = sW2 + n * 192 + l2;
            u64 w0a = wn[0],   w0b = wn[1];
            u64 w1a = wn[64],  w1b = wn[65];
            u64 w2a = wn[128], w2b = wn[129];
#pragma unroll
            for (int u = 0; u < 4; u++) {
                float r = sC[u] * invf[u];
                u64 rp = pack2(r, r);
                a0a[u] = fma2(rp, w0a, a0a[u]); a0b[u] = fma2(rp, w0b, a0b[u]);
                a1a[u] = fma2(rp, w1a, a1a[u]); a1b[u] = fma2(rp, w1b, a1b[u]);
                a2a[u] = fma2(rp, w2a, a2a[u]); a2b[u] = fma2(rp, w2b, a2b[u]);
                float tn = fmaf(c2[u], sC[u], -sP[u]);
                sP[u] = sC[u]; sC[u] = tn;
            }
        }
#pragma unroll
        for (int u = 0; u < 4; u++) {
            if (dst[u] != cur) {
                FLUSH(cur);
                cur = dst[u];
            }
            const u64* so2 = (const u64*)(so + (size_t)src[u] * 384);
            u64 g0a = mul2(a0a[u], so2[l2]);       u64 g0b = mul2(a0b[u], so2[l2 + 1]);
            u64 g1a = mul2(a1a[u], so2[64 + l2]);  u64 g1b = mul2(a1b[u], so2[64 + l2 + 1]);
            ans0 = fma2(a2a[u], so2[128 + l2],     ans0);
            ans1 = fma2(a2b[u], so2[128 + l2 + 1], ans1);

            const u64* nv2 = (const u64*)(nv_r + (size_t)src[u] * 384);
            {
                u64 up = pack2(ux[u], ux[u]);
                anv0 = fma2(nv2[l2],     g0a, fma2(up, g1a, anv0));
                anv1 = fma2(nv2[l2 + 1], g0b, fma2(up, g1b, anv1));
            }
            {
                u64 up = pack2(uy[u], uy[u]);
                anv2 = fma2(nv2[64 + l2],     g0a, fma2(up, g1a, anv2));
                anv3 = fma2(nv2[64 + l2 + 1], g0b, fma2(up, g1b, anv3));
            }
            {
                u64 up = pack2(uz[u], uz[u]);
                anv4 = fma2(nv2[128 + l2],     g0a, fma2(up, g1a, anv4));
                anv5 = fma2(nv2[128 + l2 + 1], g0b, fma2(up, g1b, anv5));
            }
        }
    }
    FLUSH(cur);
#undef FLUSH
}

// ---------------- host launch ----------------
extern "C" void kernel_launch(void* const* d_in, const int* in_sizes, int n_in,
                              void* d_out, int out_size) {
    const int*   z            = (const int*)d_in[0];
    const int*   edge         = (const int*)d_in[1];
    const float* edge_diff    = (const float*)d_in[2];
    const float* edge_dist    = (const float*)d_in[3];
    const float* embed        = (const float*)d_in[4];
    const float* msg_filter_w = (const float*)d_in[5];
    const float* msg_filter_b = (const float*)d_in[6];
    const float* msg_w1       = (const float*)d_in[7];
    const float* msg_b1       = (const float*)d_in[8];
    const float* msg_w2       = (const float*)d_in[9];
    const float* msg_b2       = (const float*)d_in[10];
    const float* upd_U_w      = (const float*)d_in[11];
    const float* upd_U_b      = (const float*)d_in[12];
    const float* upd_V_w      = (const float*)d_in[13];
    const float* upd_V_b      = (const float*)d_in[14];
    const float* upd_w1       = (const float*)d_in[15];
    const float* upd_b1       = (const float*)d_in[16];
    const float* upd_w2       = (const float*)d_in[17];
    const float* upd_b2       = (const float*)d_in[18];
    const float* ro_w1        = (const float*)d_in[19];
    const float* ro_b1        = (const float*)d_in[20];
    const float* ro_w2        = (const float*)d_in[21];
    const float* ro_b2        = (const float*)d_in[22];
    float* out = (float*)d_out;

    float *ns, *nvA, *nvB, *big, *UV, *UVw, *UVb;
    cudaGetSymbolAddress((void**)&ns,  g_ns);
    cudaGetSymbolAddress((void**)&nvA, g_nvA);
    cudaGetSymbolAddress((void**)&nvB, g_nvB);
    cudaGetSymbolAddress((void**)&big, g_big);
    cudaGetSymbolAddress((void**)&UV,  g_UV);
    cudaGetSymbolAddress((void**)&UVw, g_UVw);
    cudaGetSymbolAddress((void**)&UVb, g_UVb);

    cudaFuncSetAttribute(fused_mlp<128, 3, 0, false>, cudaFuncAttributeMaxDynamicSharedMemorySize, FUSED_SMEM);
    cudaFuncSetAttribute(fused_mlp<128, 3, 1, false>, cudaFuncAttributeMaxDynamicSharedMemorySize, FUSED_SMEM);
    cudaFuncSetAttribute(fused_mlp<256, 3, 0, true>,  cudaFuncAttributeMaxDynamicSharedMemorySize, FUSED_SMEM);
    cudaFuncSetAttribute(fused_mlp<128, 1, 2, false>, cudaFuncAttributeMaxDynamicSharedMemorySize, FUSED_SMEM);

    init_kernel<<<(N_NODES * 3 * H + 255) / 256, 256>>>(z, embed);
    hist_kernel<<<(N_EDGES + 255) / 256, 256>>>(edge);
    scan_kernel<<<1, 1024>>>();
    build_kernel<<<(N_EDGES + 255) / 256, 256>>>(edge, edge_diff, edge_dist);
    pack_uv_kernel<<<(3 * 128 * 256 + 255) / 256, 256>>>(upd_U_w, upd_U_b, upd_V_w, upd_V_b);

    const int mlp_grid = (N_NODES + 63) / 64;

    for (int l = 0; l < 3; l++) {
        if (l == 0)
            fused_mlp<128, 3, 0, false><<<mlp_grid, 256, FUSED_SMEM>>>(
                ns, msg_w1 + (size_t)l * 128 * 128, msg_b1 + l * 128,
                msg_w2 + (size_t)l * 128 * 384, msg_b2 + l * 384, big, N_NODES);
        else
            fused_mlp<128, 3, 1, false><<<mlp_grid, 256, FUSED_SMEM>>>(
                ns, msg_w1 + (size_t)l * 128 * 128, msg_b1 + l * 128,
                msg_w2 + (size_t)l * 128 * 384, msg_b2 + l * 384, big, N_NODES);
        edge_seg_kernel<<<(N_EDGES / 16 * 32) / 256, 256>>>(
            msg_filter_w + (size_t)l * 20 * 384, msg_filter_b + l * 384,
            big, nvA, ns, nvB);
        {
            dim3 g(2, (N_NODES * 3 + 127) / 128);
            mma_gemm<128, false><<<g, 256>>>(nvB, UVw + (size_t)l * 128 * 256,
                                             UVb + l * 256, UV, N_NODES * 3, 256, 128);
        }
        fused_mlp<256, 3, 0, true><<<mlp_grid, 256, FUSED_SMEM>>>(
            ns, upd_w1 + (size_t)l * 256 * 128, upd_b1 + l * 128,
            upd_w2 + (size_t)l * 128 * 384, upd_b2 + l * 384, big, N_NODES);
    }

    fused_mlp<128, 1, 2, false><<<mlp_grid, 256, FUSED_SMEM>>>(
        ns, ro_w1, ro_b1, ro_w2, ro_b2, out, N_NODES);
}

// round 16
// speedup vs baseline: 1.0337x; 1.0337x over previous
#include <cuda_runtime.h>
#include <cuda_bf16.h>
#include <math.h>

#define N_NODES 10000
#define N_EDGES 160000
#define H 128
#define E_RBF 20
#define CUTOFF 5.0f
#define PI_F 3.14159265358979f

typedef unsigned long long u64;
typedef unsigned int u32;

// ---------------- scratch ----------------
__device__ float g_ns[N_NODES * H];
__device__ float g_nvA[N_NODES * 3 * H];
__device__ float g_nvB[N_NODES * 3 * H];
__device__ float g_hidden[N_NODES * H];
__device__ float g_big[N_NODES * 3 * H];
__device__ float g_UV[N_NODES * 3 * 256];
__device__ float g_mlpin[N_NODES * 2 * H];
__device__ float g_UVw[3 * 128 * 256];
__device__ float g_UVb[3 * 256];
// CSR sort + sorted-position per-edge precompute
__device__ int    g_count[N_NODES];
__device__ int    g_offset[N_NODES + 1];
__device__ int    g_ssrc[N_EDGES];
__device__ int    g_sdst[N_EDGES];
__device__ float4 g_eunit[N_EDGES];       // {ux, uy, uz, fcut}
__device__ float4 g_rbf4[N_EDGES * 5];    // rbf_n * fcut / d, 20 per edge (layer-invariant)

// ---------------- helpers ----------------
__device__ __forceinline__ u64 pack2(float x, float y) {
    u64 r; asm("mov.b64 %0,{%1,%2};" : "=l"(r) : "f"(x), "f"(y)); return r;
}
__device__ __forceinline__ void unpack2(u64 v, float& x, float& y) {
    asm("mov.b64 {%0,%1},%2;" : "=f"(x), "=f"(y) : "l"(v));
}
__device__ __forceinline__ u64 fma2(u64 a, u64 b, u64 c) {
    u64 d; asm("fma.rn.f32x2 %0,%1,%2,%3;" : "=l"(d) : "l"(a), "l"(b), "l"(c)); return d;
}
__device__ __forceinline__ u64 mul2(u64 a, u64 b) {
    u64 d; asm("mul.rn.f32x2 %0,%1,%2;" : "=l"(d) : "l"(a), "l"(b)); return d;
}
__device__ __forceinline__ void red4(float* p, float x, float y, float z, float w) {
    asm volatile("red.global.add.v4.f32 [%0], {%1,%2,%3,%4};"
                 :: "l"(p), "f"(x), "f"(y), "f"(z), "f"(w) : "memory");
}
__device__ __forceinline__ float silu_f(float x) { return x / (1.0f + expf(-x)); }
__device__ __forceinline__ float tf32rna(float x) {
    u32 r; asm("cvt.rna.tf32.f32 %0, %1;" : "=r"(r) : "f"(x));
    return __uint_as_float(r);
}

#define MMA_TF32(cc, aa, bb)                                                      \
    asm volatile("mma.sync.aligned.m16n8k8.row.col.f32.tf32.tf32.f32 "            \
                 "{%0,%1,%2,%3},{%4,%5,%6,%7},{%8,%9},{%0,%1,%2,%3};"             \
                 : "+f"((cc)[0]), "+f"((cc)[1]), "+f"((cc)[2]), "+f"((cc)[3])     \
                 : "r"((aa)[0]), "r"((aa)[1]), "r"((aa)[2]), "r"((aa)[3]),        \
                   "r"((bb)[0]), "r"((bb)[1]))

// ---------------- init ----------------
__global__ void init_kernel(const int* __restrict__ z, const float* __restrict__ embed) {
    int i = blockIdx.x * blockDim.x + threadIdx.x;
    if (i >= N_NODES * 3 * H) return;
    g_nvA[i] = 0.0f;
    g_nvB[i] = 0.0f;
    if (i < N_NODES * H) {
        int n = i >> 7, h = i & 127;
        g_ns[i] = embed[z[n] * H + h];
    }
    if (i < N_NODES) g_count[i] = 0;
}

// ---------------- dst histogram ----------------
__global__ void hist_kernel(const int* __restrict__ edge) {
    int e = blockIdx.x * blockDim.x + threadIdx.x;
    if (e >= N_EDGES) return;
    atomicAdd(&g_count[edge[2 * e]], 1);
}

// ---------------- exclusive scan of counts ----------------
__global__ __launch_bounds__(1024)
void scan_kernel() {
    __shared__ int part[1024];
    const int t = threadIdx.x;
    const int CH = (N_NODES + 1023) / 1024;
    const int base = t * CH;
    int s = 0;
    for (int i = 0; i < CH; i++) {
        int idx = base + i;
        if (idx < N_NODES) s += g_count[idx];
    }
    part[t] = s;
    __syncthreads();
    for (int off = 1; off < 1024; off <<= 1) {
        int v = (t >= off) ? part[t - off] : 0;
        __syncthreads();
        part[t] += v;
        __syncthreads();
    }
    int run = (t > 0) ? part[t - 1] : 0;
    for (int i = 0; i < CH; i++) {
        int idx = base + i;
        if (idx < N_NODES) {
            g_offset[idx] = run;
            run += g_count[idx];
            g_count[idx] = 0;
        }
    }
    if (t == 1023) g_offset[N_NODES] = part[1023];
}

// ---------------- build sorted arrays + per-edge invariants (incl. rbf) ----------------
__global__ void build_kernel(const int* __restrict__ edge,
                             const float* __restrict__ ediff,
                             const float* __restrict__ edist) {
    int e = blockIdx.x * blockDim.x + threadIdx.x;
    if (e >= N_EDGES) return;
    int dst = edge[2 * e], src = edge[2 * e + 1];
    int pos = g_offset[dst] + atomicAdd(&g_count[dst], 1);
    float d = edist[e];
    float sn, cs;
    sincosf(d * (PI_F / CUTOFF), &sn, &cs);
    float fcv = (d < CUTOFF) ? 0.5f * (cs + 1.0f) : 0.0f;
    float inv = 1.0f / d;
    g_ssrc[pos]  = src;
    g_sdst[pos]  = dst;
    g_eunit[pos] = make_float4(ediff[3 * e] * inv, ediff[3 * e + 1] * inv,
                               ediff[3 * e + 2] * inv, fcv);
    // rbf_n * fcut / d via the EXACT recurrence the edge kernel used (bit-identical)
    float invf = inv * fcv;
    float sC = sn, sP = 0.0f, c2 = 2.0f * cs;
    float rf[E_RBF];
#pragma unroll
    for (int n = 0; n < E_RBF; n++) {
        rf[n] = sC * invf;
        float tn = fmaf(c2, sC, -sP);
        sP = sC; sC = tn;
    }
#pragma unroll
    for (int q = 0; q < 5; q++)
        g_rbf4[(size_t)pos * 5 + q] =
            make_float4(rf[4 * q], rf[4 * q + 1], rf[4 * q + 2], rf[4 * q + 3]);
}

// ---------------- pack [U_w | V_w] ----------------
__global__ void pack_uv_kernel(const float* __restrict__ Uw, const float* __restrict__ Ub,
                               const float* __restrict__ Vw, const float* __restrict__ Vb) {
    int i = blockIdx.x * blockDim.x + threadIdx.x;
    if (i < 3 * 128 * 256) {
        int l = i / (128 * 256), r = (i / 256) & 127, c = i & 255;
        g_UVw[i] = (c < 128) ? Uw[(size_t)l * 16384 + r * 128 + c]
                             : Vw[(size_t)l * 16384 + r * 128 + (c - 128)];
    }
    if (i < 3 * 256) {
        int l = i / 256, c = i & 255;
        g_UVb[i] = (c < 128) ? Ub[l * 128 + c] : Vb[l * 128 + (c - 128)];
    }
}

// ---------------- TF32 tensor-core GEMM (R8 structure, BM templated) ----------------
template<int BM, bool SILU>
__global__ __launch_bounds__(256, 2)
void mma_gemm(const float* __restrict__ A, const float* __restrict__ B,
              const float* __restrict__ bias, float* __restrict__ C,
              int M, int N, int K) {
    constexpr int MT = BM / 32;
    __shared__ float As[2][BM][20];
    __shared__ float Bs[2][16][136];
    const int t    = threadIdx.x;
    const int w    = t >> 5, lane = t & 31;
    const int g    = lane >> 2, tg = lane & 3;
    const int wm   = (w & 1) * (BM / 2);
    const int wn   = (w >> 1) * 32;
    const int m0   = blockIdx.y * BM;
    const int n0   = blockIdx.x * 128;

    float c[MT][4][4];
#pragma unroll
    for (int i = 0; i < MT; i++)
#pragma unroll
        for (int j = 0; j < 4; j++)
#pragma unroll
            for (int q = 0; q < 4; q++) c[i][j][q] = 0.0f;

    constexpr int ALD = (BM == 128) ? 2 : 1;
    int ar[2], ak[2];
#pragma unroll
    for (int i = 0; i < ALD; i++) {
        int s = t * ALD + i;
        ar[i] = s >> 2;
        ak[i] = (s & 3) << 2;
    }
    const int bs  = t * 2;
    const int bk0 = bs >> 5,        bn0 = (bs & 31) << 2;
    const int bk1 = (bs + 1) >> 5,  bn1 = ((bs + 1) & 31) << 2;

    float4 va[2], vb0, vb1;
    const float4 z4 = make_float4(0.f, 0.f, 0.f, 0.f);

#pragma unroll
    for (int i = 0; i < ALD; i++)
        va[i] = (m0 + ar[i] < M) ? *(const float4*)(A + (size_t)(m0 + ar[i]) * K + ak[i]) : z4;
    vb0 = *(const float4*)(B + (size_t)bk0 * N + n0 + bn0);
    vb1 = *(const float4*)(B + (size_t)bk1 * N + n0 + bn1);
    {
#pragma unroll
        for (int i = 0; i < ALD; i++) {
            float* p = &As[0][ar[i]][ak[i]];
            p[0] = tf32rna(va[i].x); p[1] = tf32rna(va[i].y);
            p[2] = tf32rna(va[i].z); p[3] = tf32rna(va[i].w);
        }
        float* q0 = &Bs[0][bk0][bn0];
        q0[0] = tf32rna(vb0.x); q0[1] = tf32rna(vb0.y); q0[2] = tf32rna(vb0.z); q0[3] = tf32rna(vb0.w);
        float* q1 = &Bs[0][bk1][bn1];
        q1[0] = tf32rna(vb1.x); q1[1] = tf32rna(vb1.y); q1[2] = tf32rna(vb1.z); q1[3] = tf32rna(vb1.w);
    }
    __syncthreads();

    const int nk = K >> 4;
    for (int kt = 0; kt < nk; kt++) {
        const int s = kt & 1;
        if (kt + 1 < nk) {
            const int k0 = (kt + 1) << 4;
#pragma unroll
            for (int i = 0; i < ALD; i++)
                va[i] = (m0 + ar[i] < M) ? *(const float4*)(A + (size_t)(m0 + ar[i]) * K + k0 + ak[i]) : z4;
            vb0 = *(const float4*)(B + (size_t)(k0 + bk0) * N + n0 + bn0);
            vb1 = *(const float4*)(B + (size_t)(k0 + bk1) * N + n0 + bn1);
        }
#pragma unroll
        for (int kk = 0; kk < 2; kk++) {
            const int kb = kk * 8;
            u32 a[MT][4], b[4][2];
#pragma unroll
            for (int mt = 0; mt < MT; mt++) {
                const int r = wm + mt * 16 + g;
                a[mt][0] = __float_as_uint(As[s][r][kb + tg]);
                a[mt][1] = __float_as_uint(As[s][r + 8][kb + tg]);
                a[mt][2] = __float_as_uint(As[s][r][kb + tg + 4]);
                a[mt][3] = __float_as_uint(As[s][r + 8][kb + tg + 4]);
            }
#pragma unroll
            for (int nt = 0; nt < 4; nt++) {
                const int col = wn + nt * 8 + g;
                b[nt][0] = __float_as_uint(Bs[s][kb + tg][col]);
                b[nt][1] = __float_as_uint(Bs[s][kb + tg + 4][col]);
            }
#pragma unroll
            for (int mt = 0; mt < MT; mt++)
#pragma unroll
                for (int nt = 0; nt < 4; nt++)
                    MMA_TF32(c[mt][nt], a[mt], b[nt]);
        }
        if (kt + 1 < nk) {
            const int ss = s ^ 1;
#pragma unroll
            for (int i = 0; i < ALD; i++) {
                float* p = &As[ss][ar[i]][ak[i]];
                p[0] = tf32rna(va[i].x); p[1] = tf32rna(va[i].y);
                p[2] = tf32rna(va[i].z); p[3] = tf32rna(va[i].w);
            }
            float* q0 = &Bs[ss][bk0][bn0];
            q0[0] = tf32rna(vb0.x); q0[1] = tf32rna(vb0.y); q0[2] = tf32rna(vb0.z); q0[3] = tf32rna(vb0.w);
            float* q1 = &Bs[ss][bk1][bn1];
            q1[0] = tf32rna(vb1.x); q1[1] = tf32rna(vb1.y); q1[2] = tf32rna(vb1.z); q1[3] = tf32rna(vb1.w);
            __syncthreads();
        }
    }

#pragma unroll
    for (int nt = 0; nt < 4; nt++) {
        const int col = n0 + wn + nt * 8 + 2 * tg;
        const float2 bb = *(const float2*)&bias[col];
#pragma unroll
        for (int mt = 0; mt < MT; mt++) {
            const int r0 = m0 + wm + mt * 16 + g;
            float v0 = c[mt][nt][0] + bb.x, v1 = c[mt][nt][1] + bb.y;
            float v2 = c[mt][nt][2] + bb.x, v3 = c[mt][nt][3] + bb.y;
            if (SILU) { v0 = silu_f(v0); v1 = silu_f(v1); v2 = silu_f(v2); v3 = silu_f(v3); }
            if (r0 < M)     *(float2*)(C + (size_t)r0 * N + col)       = make_float2(v0, v1);
            if (r0 + 8 < M) *(float2*)(C + (size_t)(r0 + 8) * N + col) = make_float2(v2, v3);
        }
    }
}

// ---------------- edge kernel: 16 sorted edges/warp, precomputed rbf, seg reduction ----------------
__global__ __launch_bounds__(256, 2)
void edge_seg_kernel(const float* __restrict__ Wf,
                     const float* __restrict__ bf,
                     const float* __restrict__ so,
                     const float* __restrict__ nv_r,
                     float* __restrict__ ns_acc,
                     float* __restrict__ nv_acc)
{
    __shared__ float sW[E_RBF * 384 + 384];
    for (int i = threadIdx.x; i < E_RBF * 384; i += blockDim.x) sW[i] = Wf[i];
    for (int i = threadIdx.x; i < 384; i += blockDim.x) sW[E_RBF * 384 + i] = bf[i];
    __syncthreads();
    const u64* sW2 = (const u64*)sW;
    const u64* sB2 = (const u64*)(sW + E_RBF * 384);

    const int lane = threadIdx.x & 31;
    const int l2   = lane * 2;
    const int warp = (blockIdx.x * blockDim.x + threadIdx.x) >> 5;
    const int jb   = warp * 16;
    if (jb >= N_EDGES) return;

    const u64 Z = pack2(0.0f, 0.0f);
    u64 ans0 = Z, ans1 = Z;
    u64 anv0 = Z, anv1 = Z, anv2 = Z, anv3 = Z, anv4 = Z, anv5 = Z;
    int cur = g_sdst[jb];

#define FLUSH(D)                                                                  \
    do {                                                                          \
        float f0, f1, f2, f3;                                                     \
        unpack2(ans0, f0, f1); unpack2(ans1, f2, f3);                             \
        red4(ns_acc + (size_t)(D) * H + 4 * lane, f0, f1, f2, f3);                \
        float* bp_ = nv_acc + (size_t)(D) * 384 + 4 * lane;                       \
        unpack2(anv0, f0, f1); unpack2(anv1, f2, f3); red4(bp_,       f0, f1, f2, f3); \
        unpack2(anv2, f0, f1); unpack2(anv3, f2, f3); red4(bp_ + 128, f0, f1, f2, f3); \
        unpack2(anv4, f0, f1); unpack2(anv5, f2, f3); red4(bp_ + 256, f0, f1, f2, f3); \
        ans0 = ans1 = anv0 = anv1 = anv2 = anv3 = anv4 = anv5 = Z;                \
    } while (0)

    for (int j = jb; j < jb + 16; j += 4) {
        int src[4], dst[4];
        float ux[4], uy[4], uz[4];
        u64 a0a[4], a0b[4], a1a[4], a1b[4], a2a[4], a2b[4];
#pragma unroll
        for (int u = 0; u < 4; u++) {
            int p = j + u;
            src[u] = g_ssrc[p];
            dst[u] = g_sdst[p];
            float4 un = g_eunit[p];
            ux[u] = un.x; uy[u] = un.y; uz[u] = un.z;
            u64 fcp = pack2(un.w, un.w);
            a0a[u] = mul2(sB2[l2],       fcp); a0b[u] = mul2(sB2[l2 + 1],       fcp);
            a1a[u] = mul2(sB2[64 + l2],  fcp); a1b[u] = mul2(sB2[64 + l2 + 1],  fcp);
            a2a[u] = mul2(sB2[128 + l2], fcp); a2b[u] = mul2(sB2[128 + l2 + 1], fcp);
        }
        // filter accumulation with precomputed rbf (software-pipelined broadcast loads)
        float4 rfc[4], rfn[4];
#pragma unroll
        for (int u = 0; u < 4; u++) rfc[u] = g_rbf4[(size_t)(j + u) * 5];
#pragma unroll
        for (int n4 = 0; n4 < 5; n4++) {
            if (n4 < 4) {
#pragma unroll
                for (int u = 0; u < 4; u++)
                    rfn[u] = g_rbf4[(size_t)(j + u) * 5 + n4 + 1];
            }
#pragma unroll
            for (int nn = 0; nn < 4; nn++) {
                const int n = n4 * 4 + nn;
                const u64* wn = sW2 + n * 192 + l2;
                u64 w0a = wn[0],   w0b = wn[1];
                u64 w1a = wn[64],  w1b = wn[65];
                u64 w2a = wn[128], w2b = wn[129];
#pragma unroll
                for (int u = 0; u < 4; u++) {
                    float r = (nn == 0) ? rfc[u].x : (nn == 1) ? rfc[u].y
                            : (nn == 2) ? rfc[u].z : rfc[u].w;
                    u64 rp = pack2(r, r);
                    a0a[u] = fma2(rp, w0a, a0a[u]); a0b[u] = fma2(rp, w0b, a0b[u]);
                    a1a[u] = fma2(rp, w1a, a1a[u]); a1b[u] = fma2(rp, w1b, a1b[u]);
                    a2a[u] = fma2(rp, w2a, a2a[u]); a2b[u] = fma2(rp, w2b, a2b[u]);
                }
            }
#pragma unroll
            for (int u = 0; u < 4; u++) rfc[u] = rfn[u];
        }
#pragma unroll
        for (int u = 0; u < 4; u++) {
            if (dst[u] != cur) {
                FLUSH(cur);
                cur = dst[u];
            }
            const u64* so2 = (const u64*)(so + (size_t)src[u] * 384);
            u64 g0a = mul2(a0a[u], so2[l2]);       u64 g0b = mul2(a0b[u], so2[l2 + 1]);
            u64 g1a = mul2(a1a[u], so2[64 + l2]);  u64 g1b = mul2(a1b[u], so2[64 + l2 + 1]);
            ans0 = fma2(a2a[u], so2[128 + l2],     ans0);
            ans1 = fma2(a2b[u], so2[128 + l2 + 1], ans1);

            const u64* nv2 = (const u64*)(nv_r + (size_t)src[u] * 384);
            {
                u64 up = pack2(ux[u], ux[u]);
                anv0 = fma2(nv2[l2],     g0a, fma2(up, g1a, anv0));
                anv1 = fma2(nv2[l2 + 1], g0b, fma2(up, g1b, anv1));
            }
            {
                u64 up = pack2(uy[u], uy[u]);
                anv2 = fma2(nv2[64 + l2],     g0a, fma2(up, g1a, anv2));
                anv3 = fma2(nv2[64 + l2 + 1], g0b, fma2(up, g1b, anv3));
            }
            {
                u64 up = pack2(uz[u], uz[u]);
                anv4 = fma2(nv2[128 + l2],     g0a, fma2(up, g1a, anv4));
                anv5 = fma2(nv2[128 + l2 + 1], g0b, fma2(up, g1b, anv5));
            }
        }
    }
    FLUSH(cur);
#undef FLUSH
}

// ---------------- Vv norm + concat into mlp_in ----------------
__global__ void norm_kernel() {
    int i = blockIdx.x * blockDim.x + threadIdx.x;
    if (i >= N_NODES * H) return;
    int n = i >> 7, h = i & 127;
    size_t base = (size_t)(3 * n) * 256 + 128 + h;
    float v0 = g_UV[base], v1 = g_UV[base + 256], v2 = g_UV[base + 512];
    g_mlpin[(size_t)n * 256 + h]       = sqrtf(v0 * v0 + v1 * v1 + v2 * v2);
    g_mlpin[(size_t)n * 256 + 128 + h] = g_ns[i];
}

// ---------------- gated update ----------------
__global__ void update_kernel() {
    int i = blockIdx.x * blockDim.x + threadIdx.x;
    if (i >= N_NODES * H) return;
    int n = i >> 7, h = i & 127;
    const float* mo = g_big + (size_t)n * 384;
    float a_vv = mo[h], a_sv = mo[128 + h], a_ss = mo[256 + h];
    size_t nvb = (size_t)n * 384 + h;
    size_t uvb = (size_t)(3 * n) * 256 + h;
    float dot = 0.0f;
#pragma unroll
    for (int d = 0; d < 3; d++) {
        float u = g_UV[uvb + d * 256];
        float v = g_UV[uvb + d * 256 + 128];
        dot = fmaf(u, v, dot);
        float nvnew = g_nvB[nvb + d * 128] + a_vv * u;
        g_nvA[nvb + d * 128] = nvnew;
        g_nvB[nvb + d * 128] = nvnew;
    }
    g_ns[i] += a_sv * dot + a_ss;
}

// ---------------- host launch ----------------
static void gemm(const float* A, const float* B, const float* bias, float* C,
                 int M, int N, int K, bool silu) {
    if (N == 128) {
        dim3 g(1, (M + 63) / 64);
        if (silu) mma_gemm<64, true><<<g, 256>>>(A, B, bias, C, M, N, K);
        else      mma_gemm<64, false><<<g, 256>>>(A, B, bias, C, M, N, K);
    } else {
        dim3 g(N / 128, (M + 127) / 128);
        if (silu) mma_gemm<128, true><<<g, 256>>>(A, B, bias, C, M, N, K);
        else      mma_gemm<128, false><<<g, 256>>>(A, B, bias, C, M, N, K);
    }
}

extern "C" void kernel_launch(void* const* d_in, const int* in_sizes, int n_in,
                              void* d_out, int out_size) {
    const int*   z            = (const int*)d_in[0];
    const int*   edge         = (const int*)d_in[1];
    const float* edge_diff    = (const float*)d_in[2];
    const float* edge_dist    = (const float*)d_in[3];
    const float* embed        = (const float*)d_in[4];
    const float* msg_filter_w = (const float*)d_in[5];
    const float* msg_filter_b = (const float*)d_in[6];
    const float* msg_w1       = (const float*)d_in[7];
    const float* msg_b1       = (const float*)d_in[8];
    const float* msg_w2       = (const float*)d_in[9];
    const float* msg_b2       = (const float*)d_in[10];
    const float* upd_U_w      = (const float*)d_in[11];
    const float* upd_U_b      = (const float*)d_in[12];
    const float* upd_V_w      = (const float*)d_in[13];
    const float* upd_V_b      = (const float*)d_in[14];
    const float* upd_w1       = (const float*)d_in[15];
    const float* upd_b1       = (const float*)d_in[16];
    const float* upd_w2       = (const float*)d_in[17];
    const float* upd_b2       = (const float*)d_in[18];
    const float* ro_w1        = (const float*)d_in[19];
    const float* ro_b1        = (const float*)d_in[20];
    const float* ro_w2        = (const float*)d_in[21];
    const float* ro_b2        = (const float*)d_in[22];
    float* out = (float*)d_out;

    float *ns, *nvA, *nvB, *hidden, *big, *UV, *mlpin, *UVw, *UVb;
    cudaGetSymbolAddress((void**)&ns,     g_ns);
    cudaGetSymbolAddress((void**)&nvA,    g_nvA);
    cudaGetSymbolAddress((void**)&nvB,    g_nvB);
    cudaGetSymbolAddress((void**)&hidden, g_hidden);
    cudaGetSymbolAddress((void**)&big,    g_big);
    cudaGetSymbolAddress((void**)&UV,     g_UV);
    cudaGetSymbolAddress((void**)&mlpin,  g_mlpin);
    cudaGetSymbolAddress((void**)&UVw,    g_UVw);
    cudaGetSymbolAddress((void**)&UVb,    g_UVb);

    init_kernel<<<(N_NODES * 3 * H + 255) / 256, 256>>>(z, embed);
    hist_kernel<<<(N_EDGES + 255) / 256, 256>>>(edge);
    scan_kernel<<<1, 1024>>>();
    build_kernel<<<(N_EDGES + 255) / 256, 256>>>(edge, edge_diff, edge_dist);
    pack_uv_kernel<<<(3 * 128 * 256 + 255) / 256, 256>>>(upd_U_w, upd_U_b, upd_V_w, upd_V_b);

    for (int l = 0; l < 3; l++) {
        gemm(ns, msg_w1 + (size_t)l * 128 * 128, msg_b1 + l * 128, hidden,
             N_NODES, 128, 128, true);
        gemm(hidden, msg_w2 + (size_t)l * 128 * 384, msg_b2 + l * 384, big,
             N_NODES, 384, 128, false);
        edge_seg_kernel<<<(N_EDGES / 16 * 32) / 256, 256>>>(
            msg_filter_w + (size_t)l * 20 * 384, msg_filter_b + l * 384,
            big, nvA, ns, nvB);
        gemm(nvB, UVw + (size_t)l * 128 * 256, UVb + l * 256, UV,
             N_NODES * 3, 256, 128, false);
        norm_kernel<<<(N_NODES * H + 255) / 256, 256>>>();
        gemm(mlpin, upd_w1 + (size_t)l * 256 * 128, upd_b1 + l * 128, hidden,
             N_NODES, 128, 256, true);
        gemm(hidden, upd_w2 + (size_t)l * 128 * 384, upd_b2 + l * 384, big,
             N_NODES, 384, 128, false);
        update_kernel<<<(N_NODES * H + 255) / 256, 256>>>();
    }

    gemm(ns, ro_w1, ro_b1, hidden, N_NODES, 128, 128, true);
    gemm(hidden, ro_w2, ro_b2, out, N_NODES, 128, 128, false);
}